// round 15
// baseline (speedup 1.0000x reference)
#include <cuda_runtime.h>
#include <cuda_bf16.h>
#include <stdint.h>

#define IN_F   4096
#define OUT_F  11008
#define BATCH  16
#define SPLITS 4
#define KSTEPS_TOT   (IN_F / 16)            // 256 k16-steps
#define KSTEPS_SPLIT (KSTEPS_TOT / SPLITS)  // 64
#define CKS    8                            // ksteps per smem chunk
#define NCHUNK (KSTEPS_SPLIT / CKS)         // 8
#define CHUNK_INTS (CKS * 16)               // 128 ints per row per chunk
#define MTILE  64
#define THREADS 128

// Static scratch (allocations forbidden).
__device__ __align__(16) uint32_t g_bfrag[KSTEPS_TOT * 256];      // [ks][j(4)][lane(32)][p(2)]
__device__ __align__(16) float    g_part[SPLITS * BATCH * OUT_F]; // [s][b][o]

// Pack two floats into one bf16x2 reg (low = first).
__device__ __forceinline__ uint32_t pack_bf16x2(float ev, float od) {
    __nv_bfloat162 h = __floats2bfloat162_rn(ev, od);   // .x = ev (low), .y = od (high)
    return *(uint32_t*)&h;
}

__device__ __forceinline__ uint32_t smem_u32(const void* p) {
    uint32_t a;
    asm("{ .reg .u64 t; cvta.to.shared.u64 t, %1; cvt.u32.u64 %0, t; }" : "=r"(a) : "l"(p));
    return a;
}

// m16n8k16 row.col bf16 MMA, fp32 accumulate in place.
__device__ __forceinline__ void mma16816(float* c, const uint32_t* a, uint32_t b0, uint32_t b1) {
    asm volatile(
        "mma.sync.aligned.m16n8k16.row.col.f32.bf16.bf16.f32 "
        "{%0,%1,%2,%3}, {%4,%5,%6,%7}, {%8,%9}, {%0,%1,%2,%3};"
        : "+f"(c[0]), "+f"(c[1]), "+f"(c[2]), "+f"(c[3])
        : "r"(a[0]), "r"(a[1]), "r"(a[2]), "r"(a[3]), "r"(b0), "r"(b1));
}

// ldmatrix x4: A fragment (a0..a3) for m16n8k16 from swizzled smem.
__device__ __forceinline__ void ldmatrix_x4(uint32_t* a, uint32_t addr) {
    asm volatile("ldmatrix.sync.aligned.m8n8.x4.shared.b16 {%0,%1,%2,%3}, [%4];"
                 : "=r"(a[0]), "=r"(a[1]), "=r"(a[2]), "=r"(a[3]) : "r"(addr));
}

// ---------------------------------------------------------------------------
// Kernel 1: build B fragments, one thread per fragment reg (65536 threads).
// Word layout: ks*256 + j*64 + l*2 + p  (j = n-tile 0,1 hi / 2,3 lo; p = k-half)
// so the gemm reads (p0,p1) with one LDS.64. Fully coalesced stores.
// ---------------------------------------------------------------------------
__global__ void prep_kernel(const float* __restrict__ x) {
    int idx = blockIdx.x * blockDim.x + threadIdx.x;   // 65536
    int p  = idx & 1;
    int l  = (idx >> 1) & 31;
    int j  = (idx >> 6) & 3;
    int ks = idx >> 8;
    int g = l >> 2, t = l & 3;
    int br = (j & 1) * 8 + g;
    int k  = ks * 16 + 2 * t + 8 * p;

    float2 v = *(const float2*)(x + (size_t)br * IN_F + k);
    float h0 = __bfloat162float(__float2bfloat16(v.x));
    float h1 = __bfloat162float(__float2bfloat16(v.y));
    uint32_t out;
    if (j < 2) out = pack_bf16x2(h0, h1);              // hi part
    else       out = pack_bf16x2(v.x - h0, v.y - h1);  // lo residual
    g_bfrag[idx] = out;
}

// ---------------------------------------------------------------------------
// Kernel 2: HMMA GEMM with coalesced A staging through swizzled smem.
// A: full-line LDG.128 -> int->bf16 convert -> STS (XOR swizzle) -> ldmatrix.
// B: prebuilt fragments, double-buffered smem. Split-K over grid.y.
// ---------------------------------------------------------------------------
__global__ void __launch_bounds__(THREADS) gemm_kernel(const int* __restrict__ W) {
    __shared__ __align__(16) unsigned char sa[2 * 16384];   // A bf16, swizzled
    __shared__ __align__(16) uint32_t sbv[2 * CKS * 256];   // B frags, 2 x 8 KB

    const int tid = threadIdx.x, wid = tid >> 5, l = tid & 31;
    const int g = l >> 2, t = l & 3;
    const int s = blockIdx.y;
    const int m0cta = blockIdx.x * MTILE;
    const int ksbase = s * KSTEPS_SPLIT;

    // Staging roles: 8 lanes cover one full 128B line per instruction.
    const int srow = tid >> 3;        // 0..15 (+16*pp, +32*h)
    const int sseg = tid & 7;

    // ldmatrix lane roles.
    const int lrow = wid * 16 + (l & 7) + ((l >> 3) & 1) * 8;   // row in 64-tile
    const int lswz = lrow & 7;
    const int lkh  = (l >> 3) >> 1;                              // k-half
    const uint32_t sa_u32 = smem_u32(sa);

    const uint4* bsrc = (const uint4*)(g_bfrag + ksbase * 256);

    int4  wq[8];
    uint4 bstage[4];

#define LDA_HALF(c, h) do {                                                   \
        const int base_int = ksbase * 16 + (c) * CHUNK_INTS;                  \
        _Pragma("unroll")                                                     \
        for (int pp = 0; pp < 2; pp++)                                        \
        _Pragma("unroll")                                                     \
        for (int li = 0; li < 4; li++) {                                      \
            int row = (h) * 32 + pp * 16 + srow;                              \
            wq[pp * 4 + li] = *(const int4*)(W + (size_t)(m0cta + row) * IN_F \
                                             + base_int + li * 32 + sseg * 4);\
        }                                                                     \
    } while (0)

#define STS_A(buf, h) do {                                                    \
        _Pragma("unroll")                                                     \
        for (int pp = 0; pp < 2; pp++)                                        \
        _Pragma("unroll")                                                     \
        for (int li = 0; li < 4; li++) {                                      \
            int4 v = wq[pp * 4 + li];                                         \
            int row = (h) * 32 + pp * 16 + srow;                              \
            uint32_t u0 = pack_bf16x2((float)v.x, (float)v.y);                \
            uint32_t u1 = pack_bf16x2((float)v.z, (float)v.w);                \
            uint32_t off = (buf) * 16384 + row * 256                          \
                         + ((((li * 4) + (sseg >> 1)) ^ (row & 7)) << 4)      \
                         + ((sseg & 1) << 3);                                 \
            *(uint2*)(sa + off) = make_uint2(u0, u1);                         \
        }                                                                     \
    } while (0)

    float acc[16];
#pragma unroll
    for (int i = 0; i < 16; i++) acc[i] = 0.f;

#define COMPUTE(ks0, ks1) do {                                                \
        _Pragma("unroll")                                                     \
        for (int ksl = (ks0); ksl < (ks1); ksl++) {                           \
            uint32_t a[4];                                                    \
            uint32_t aaddr = sa_u32 + p * 16384 + lrow * 256                  \
                           + ((((ksl * 2) + lkh) ^ lswz) << 4);               \
            ldmatrix_x4(a, aaddr);                                            \
            const uint32_t* bb = sbv + p * 2048 + ksl * 256 + 2 * l;          \
            _Pragma("unroll")                                                 \
            for (int j = 0; j < 4; j++) {                                     \
                uint2 b2 = *(const uint2*)(bb + j * 64);                      \
                mma16816(acc + j * 4, a, b2.x, b2.y);                         \
            }                                                                 \
        }                                                                     \
    } while (0)

    // Prologue: stage chunk 0 (A halves + B) into buffer 0.
    LDA_HALF(0, 0);
#pragma unroll
    for (int j = 0; j < 4; j++) bstage[j] = bsrc[j * 128 + tid];
    STS_A(0, 0);
    LDA_HALF(0, 1);
    STS_A(0, 1);
#pragma unroll
    for (int j = 0; j < 4; j++) ((uint4*)sbv)[j * 128 + tid] = bstage[j];
    __syncthreads();

    int p = 0;
    for (int c = 0; c < NCHUNK; c++) {
        if (c + 1 < NCHUNK) {
            LDA_HALF(c + 1, 0);
#pragma unroll
            for (int j = 0; j < 4; j++) bstage[j] = bsrc[(c + 1) * 512 + j * 128 + tid];
        }
        COMPUTE(0, 4);
        if (c + 1 < NCHUNK) {
            STS_A(p ^ 1, 0);
            LDA_HALF(c + 1, 1);
        }
        COMPUTE(4, 8);
        if (c + 1 < NCHUNK) {
            STS_A(p ^ 1, 1);
#pragma unroll
            for (int j = 0; j < 4; j++)
                ((uint4*)(sbv + (p ^ 1) * 2048))[j * 128 + tid] = bstage[j];
        }
        __syncthreads();
        p ^= 1;
    }

    // Epilogue: hi + lo, transpose through smem (reuse sa), coalesced stores.
    // C frag: c0=[g][2t], c1=[g][2t+1], c2=[g+8][2t], c3=[g+8][2t+1]
    float* sep = (float*)sa;                       // [b][m_local] = 16 x 64 floats
#pragma unroll
    for (int j = 0; j < 2; j++) {
        int b0 = j * 8 + 2 * t;
        int ml = wid * 16 + g;
        sep[(b0)     * MTILE + ml]     = acc[j * 4 + 0] + acc[(j + 2) * 4 + 0];
        sep[(b0 + 1) * MTILE + ml]     = acc[j * 4 + 1] + acc[(j + 2) * 4 + 1];
        sep[(b0)     * MTILE + ml + 8] = acc[j * 4 + 2] + acc[(j + 2) * 4 + 2];
        sep[(b0 + 1) * MTILE + ml + 8] = acc[j * 4 + 3] + acc[(j + 2) * 4 + 3];
    }
    __syncthreads();

    float* pb = g_part + (size_t)s * (BATCH * OUT_F) + m0cta;
#pragma unroll
    for (int f = tid; f < BATCH * MTILE / 4; f += THREADS) {   // 256 float4s
        int b   = f >> 4;
        int seg = f & 15;
        float4 v = ((const float4*)sep)[f];
        *(float4*)(pb + (size_t)b * OUT_F + seg * 4) = v;
    }
}

// ---------------------------------------------------------------------------
// Kernel 3: sum the 4 split partials (fixed order), apply scale + bias.
// ---------------------------------------------------------------------------
__global__ void __launch_bounds__(256) reduce_kernel(const float* __restrict__ scale,
                                                     const float* __restrict__ bias,
                                                     float* __restrict__ out) {
    const int NV = BATCH * OUT_F / 4;
    int e = blockIdx.x * blockDim.x + threadIdx.x;
    if (e >= NV) return;
    int o4 = e % (OUT_F / 4);

    float4 v[SPLITS];
#pragma unroll
    for (int s = 0; s < SPLITS; s++)
        v[s] = ((const float4*)g_part)[(size_t)s * NV + e];

    float4 sum;
    sum.x = (v[0].x + v[1].x) + (v[2].x + v[3].x);
    sum.y = (v[0].y + v[1].y) + (v[2].y + v[3].y);
    sum.z = (v[0].z + v[1].z) + (v[2].z + v[3].z);
    sum.w = (v[0].w + v[1].w) + (v[2].w + v[3].w);

    float4 sc = ((const float4*)scale)[o4];
    float4 bi = ((const float4*)bias)[o4];
    float4 r;
    r.x = fmaf(sum.x, sc.x, bi.x);
    r.y = fmaf(sum.y, sc.y, bi.y);
    r.z = fmaf(sum.z, sc.z, bi.z);
    r.w = fmaf(sum.w, sc.w, bi.w);
    ((float4*)out)[e] = r;
}

extern "C" void kernel_launch(void* const* d_in, const int* in_sizes, int n_in,
                              void* d_out, int out_size) {
    const float* x     = (const float*)d_in[0];
    const int*   W     = (const int*)d_in[1];
    const float* scale = (const float*)d_in[2];
    const float* bias  = (const float*)d_in[3];
    float*       out   = (float*)d_out;

    prep_kernel<<<(KSTEPS_TOT * 256) / 256, 256>>>(x);

    dim3 grid(OUT_F / MTILE, SPLITS);          // 172 x 4 = 688 CTAs
    gemm_kernel<<<grid, THREADS>>>(W);

    int nv = BATCH * OUT_F / 4;
    reduce_kernel<<<(nv + 255) / 256, 256>>>(scale, bias, out);
}